// round 5
// baseline (speedup 1.0000x reference)
#include <cuda_runtime.h>
#include <cuda_bf16.h>
#include <math.h>

// GAT layer, fully collapsed:
//   s1 = h @ (W a1), s2 = h @ (W a2)
//   m_i = leaky(s1_i + max_j s2_j)
//   Z_i = e^{s1_i-m_i} * SUM_{s2_j > -s1_i} e^{s2_j} + e^{.2 s1_i-m_i} * SUM_{s2_j <= -s1_i} e^{.2 s2_j}
//   c_j = e^{s2_j} * SUM_{s1_i > -s2_j} g1_i + e^{.2 s2_j} * SUM_{s1_i <= -s2_j} g2_i
//   out[b] = (1/N) * (c^T h) @ W
// Threshold sums via 1024-bin bucket structure: histogram atomic returns the
// in-bin rank (one atomic per element), scatter is atomic-free, bin sums are
// gathered + shuffle-scanned. Branch selection is exact fp compare.

#define B 8
#define N 2048
#define FIN 128
#define FOUT 64
#define ALPHA 0.2f
#define NB 1024

__device__ float d_u1[FIN];
__device__ float d_u2[FIN];
__device__ float d_s1[B * N];
__device__ float d_s2[B * N];
__device__ float d_c[B * N];
__device__ float d_v[B * FIN];
__device__ int   d_ctr;

__device__ __forceinline__ float leaky(float x) { return x >= 0.f ? x : ALPHA * x; }

__device__ __forceinline__ int binOf(float x, float lo, float scale) {
    float f = (x - lo) * scale;
    f = fminf(fmaxf(f, 0.f), (float)(NB - 1));
    return (int)f;
}

// ---------------- K1: u1 = W a1, u2 = W a2; zero d_v, d_ctr ----------------
__global__ void k_prep(const float* __restrict__ W, const float* __restrict__ a) {
    int t = threadIdx.x;            // 1024 threads
    d_v[t] = 0.f;                   // B*FIN = 1024
    if (t == 0) d_ctr = 0;
    if (t < FIN) {
        float a1 = 0.f, a2 = 0.f;
#pragma unroll
        for (int f = 0; f < FOUT; f++) {
            float w = W[t * FOUT + f];
            a1 += w * a[f];
            a2 += w * a[FOUT + f];
        }
        d_u1[t] = a1;
        d_u2[t] = a2;
    }
}

// ---------------- K2: s1,s2 per row; one warp per row ----------------
__global__ void k_scores(const float* __restrict__ h) {
    __shared__ float su1[FIN], su2[FIN];
    int tid = threadIdx.x;          // 256 threads = 8 warps
    if (tid < FIN) { su1[tid] = d_u1[tid]; su2[tid] = d_u2[tid]; }
    __syncthreads();
    int warp = tid >> 5, lane = tid & 31;
    int row = blockIdx.x * 8 + warp;
    float4 hv = ((const float4*)h)[(size_t)row * (FIN / 4) + lane];
    int c = lane * 4;
    float a1 = hv.x * su1[c] + hv.y * su1[c + 1] + hv.z * su1[c + 2] + hv.w * su1[c + 3];
    float a2 = hv.x * su2[c] + hv.y * su2[c + 1] + hv.z * su2[c + 2] + hv.w * su2[c + 3];
#pragma unroll
    for (int o = 16; o; o >>= 1) {
        a1 += __shfl_xor_sync(0xffffffffu, a1, o);
        a2 += __shfl_xor_sync(0xffffffffu, a2, o);
    }
    if (lane == 0) { d_s1[row] = a1; d_s2[row] = a2; }
}

// Build the bucket structure for keys (k0,k1) with payloads (a,b) per thread.
// On exit: val/pA/pB hold elements in bin order, off[] bin starts,
// binA/binB exclusive bin prefixes, *totA/*totB grand totals.
__device__ __forceinline__ void build_struct(
    float k0, float k1, float a0, float a1v, float b0, float b1v,
    float lo, float scale,
    float* val, float* pA, float* pB, int* cnt, int* off,
    float* binA, float* binB,
    float* wsA, float* wsB, int* wsI,
    float* totA, float* totB,
    int tid, int lane, int wid)
{
    cnt[tid] = 0;
    __syncthreads();
    int bn0 = binOf(k0, lo, scale);
    int bn1 = binOf(k1, lo, scale);
    int rk0 = atomicAdd(&cnt[bn0], 1);
    int rk1 = atomicAdd(&cnt[bn1], 1);
    __syncthreads();

    // exclusive scan of counts -> off
    {
        int c = cnt[tid];
        int ci = c;
#pragma unroll
        for (int o = 1; o < 32; o <<= 1) {
            int cy = __shfl_up_sync(0xffffffffu, ci, o);
            if (lane >= o) ci += cy;
        }
        if (lane == 31) wsI[wid] = ci;
        __syncthreads();
        if (wid == 0) {
            int cw = wsI[lane];
            int cwi = cw;
#pragma unroll
            for (int o = 1; o < 32; o <<= 1) {
                int cy = __shfl_up_sync(0xffffffffu, cwi, o);
                if (lane >= o) cwi += cy;
            }
            wsI[lane] = cwi - cw;
        }
        __syncthreads();
        off[tid] = ci - c + wsI[wid];
        if (tid == 0) off[NB] = N;
    }
    __syncthreads();

    // scatter (atomic-free: rank from histogram)
    {
        int p0 = off[bn0] + rk0;
        int p1 = off[bn1] + rk1;
        val[p0] = k0;  pA[p0] = a0;  pB[p0] = b0;
        val[p1] = k1;  pA[p1] = a1v; pB[p1] = b1v;
    }
    __syncthreads();

    // gather per-bin sums, then combined exclusive scan over 1024 bins
    {
        int s = off[tid], e = off[tid + 1];
        float sa = 0.f, sb = 0.f;
        for (int p = s; p < e; p++) { sa += pA[p]; sb += pB[p]; }
        float ia = sa, ib = sb;
#pragma unroll
        for (int o = 1; o < 32; o <<= 1) {
            float ay = __shfl_up_sync(0xffffffffu, ia, o);
            float by = __shfl_up_sync(0xffffffffu, ib, o);
            if (lane >= o) { ia += ay; ib += by; }
        }
        if (lane == 31) { wsA[wid] = ia; wsB[wid] = ib; }
        __syncthreads();
        if (wid == 0) {
            float aw = wsA[lane], bw = wsB[lane];
            float awi = aw, bwi = bw;
#pragma unroll
            for (int o = 1; o < 32; o <<= 1) {
                float ay = __shfl_up_sync(0xffffffffu, awi, o);
                float by = __shfl_up_sync(0xffffffffu, bwi, o);
                if (lane >= o) { awi += ay; bwi += by; }
            }
            wsA[lane] = awi - aw; wsB[lane] = bwi - bw;
            if (lane == 31) { *totA = awi; *totB = bwi; }
        }
        __syncthreads();
        binA[tid] = ia - sa + wsA[wid];
        binB[tid] = ib - sb + wsB[wid];
    }
    __syncthreads();
}

// ---------------- K3: per-batch softmax column mass c[j] ----------------
__global__ void __launch_bounds__(1024, 1) k_attn() {
    int b = blockIdx.x;
    int tid = threadIdx.x;          // 1024
    int lane = tid & 31, wid = tid >> 5;

    __shared__ float val[N], pA[N], pB[N];
    __shared__ float binA[NB], binB[NB];
    __shared__ int   cnt[NB];
    __shared__ int   off[NB + 1];
    __shared__ float wsA[32], wsB[32];
    __shared__ int   wsI[32];
    __shared__ float bc[8];   // lo2,hi2,lo1,hi1,totA,totB

    float rs1[2], rs2[2];
    {
        const float* gs1 = d_s1 + b * N;
        const float* gs2 = d_s2 + b * N;
#pragma unroll
        for (int r = 0; r < 2; r++) {
            int i = tid + (r << 10);
            rs1[r] = gs1[i];
            rs2[r] = gs2[i];
        }
    }

    // min/max of s1, s2
    {
        float l1 = fminf(rs1[0], rs1[1]), h1 = fmaxf(rs1[0], rs1[1]);
        float l2 = fminf(rs2[0], rs2[1]), h2 = fmaxf(rs2[0], rs2[1]);
#pragma unroll
        for (int o = 16; o; o >>= 1) {
            l1 = fminf(l1, __shfl_xor_sync(0xffffffffu, l1, o));
            h1 = fmaxf(h1, __shfl_xor_sync(0xffffffffu, h1, o));
            l2 = fminf(l2, __shfl_xor_sync(0xffffffffu, l2, o));
            h2 = fmaxf(h2, __shfl_xor_sync(0xffffffffu, h2, o));
        }
        if (lane == 0) {
            val[wid] = l1; val[32 + wid] = h1; val[64 + wid] = l2; val[96 + wid] = h2;
        }
        __syncthreads();
        if (wid == 0) {
            float a0 = val[lane], a1m = val[32 + lane];
            float a2m = val[64 + lane], a3 = val[96 + lane];
#pragma unroll
            for (int o = 16; o; o >>= 1) {
                a0  = fminf(a0,  __shfl_xor_sync(0xffffffffu, a0, o));
                a1m = fmaxf(a1m, __shfl_xor_sync(0xffffffffu, a1m, o));
                a2m = fminf(a2m, __shfl_xor_sync(0xffffffffu, a2m, o));
                a3  = fmaxf(a3,  __shfl_xor_sync(0xffffffffu, a3, o));
            }
            if (lane == 0) { bc[0] = a2m; bc[1] = a3; bc[2] = a0; bc[3] = a1m; }
        }
        __syncthreads();
    }

    // ===== PASS 1: key = s2, payload (e^{s2}, e^{.2 s2}) =====
    float lo2 = bc[0], hi2 = bc[1];
    float scale2 = (hi2 > lo2) ? ((float)NB / (hi2 - lo2)) : 0.f;

    float eA0 = __expf(rs2[0]),          eA1 = __expf(rs2[1]);
    float eB0 = __expf(ALPHA * rs2[0]),  eB1 = __expf(ALPHA * rs2[1]);

    build_struct(rs2[0], rs2[1], eA0, eA1, eB0, eB1, lo2, scale2,
                 val, pA, pB, cnt, off, binA, binB, wsA, wsB, wsI,
                 &bc[4], &bc[5], tid, lane, wid);

    float g1[2], g2[2];
    {
        float smax = bc[1], tA = bc[4], tB = bc[5];
#pragma unroll
        for (int r = 0; r < 2; r++) {
            float s1 = rs1[r];
            float t = -s1;
            int qb = binOf(t, lo2, scale2);
            float SA = binA[qb], SB = binB[qb];
            int pe = off[qb + 1];
            for (int p = off[qb]; p < pe; p++) {
                if (val[p] <= t) { SA += pA[p]; SB += pB[p]; }
            }
            float Apos = tA - SA;               // sum e^{s2} over s2 > -s1
            float m = leaky(s1 + smax);
            float e1 = __expf(s1 - m);
            float e2 = __expf(ALPHA * s1 - m);
            float inv = 1.0f / (e1 * Apos + e2 * SB);
            g1[r] = e1 * inv;
            g2[r] = e2 * inv;
        }
    }
    __syncthreads();   // done reading pass-1 structure

    // ===== PASS 2: key = s1, payload (g1, g2) =====
    float lo1 = bc[2], hi1 = bc[3];
    float scale1 = (hi1 > lo1) ? ((float)NB / (hi1 - lo1)) : 0.f;

    build_struct(rs1[0], rs1[1], g1[0], g1[1], g2[0], g2[1], lo1, scale1,
                 val, pA, pB, cnt, off, binA, binB, wsA, wsB, wsI,
                 &bc[4], &bc[5], tid, lane, wid);

    {
        float tG1 = bc[4], tG2 = bc[5];
#pragma unroll
        for (int r = 0; r < 2; r++) {
            int j = tid + (r << 10);
            float s2 = rs2[r];
            float t = -s2;
            int qb = binOf(t, lo1, scale1);
            float SG1 = binA[qb], SG2 = binB[qb];
            int pe = off[qb + 1];
            for (int p = off[qb]; p < pe; p++) {
                if (val[p] <= t) { SG1 += pA[p]; SG2 += pB[p]; }
            }
            float P = tG1 - SG1;                // sum g1 over s1 > -s2
            float c = __expf(s2) * P + __expf(ALPHA * s2) * SG2;
            d_c[b * N + j] = c;
        }
    }
}

// ---------------- K4: v[b,:] = sum_j c[b,j] h[b,j,:]; last block does out ----
__global__ void k_wsum(const float* __restrict__ h, const float* __restrict__ W,
                       float* __restrict__ out) {
    __shared__ float red[8 * FIN];
    __shared__ int isLast;
    int b = blockIdx.x >> 6;              // 64 chunks per batch, grid = B*64
    int chunk = blockIdx.x & 63;
    int wid = threadIdx.x >> 5, lane = threadIdx.x & 31;   // 256 threads
    const float4* h4 = (const float4*)h;
    const float* cb = d_c + b * N;
    size_t base = (size_t)b * N * (FIN / 4);
    int j0 = chunk * 32 + wid * 4;
    float4 acc = make_float4(0.f, 0.f, 0.f, 0.f);
#pragma unroll
    for (int q = 0; q < 4; q++) {
        int j = j0 + q;
        float cj = cb[j];
        float4 hv = h4[base + (size_t)j * (FIN / 4) + lane];
        acc.x = fmaf(cj, hv.x, acc.x);
        acc.y = fmaf(cj, hv.y, acc.y);
        acc.z = fmaf(cj, hv.z, acc.z);
        acc.w = fmaf(cj, hv.w, acc.w);
    }
    ((float4*)red)[wid * 32 + lane] = acc;
    __syncthreads();
    if (threadIdx.x < FIN) {
        int k = threadIdx.x;
        float s = 0.f;
#pragma unroll
        for (int w = 0; w < 8; w++) s += red[w * FIN + k];
        atomicAdd(&d_v[b * FIN + k], s);
        __threadfence();
    }
    __syncthreads();
    if (threadIdx.x == 0) {
        int old = atomicAdd(&d_ctr, 1);
        isLast = (old == (int)gridDim.x - 1);
    }
    __syncthreads();
    if (isLast) {
        __threadfence();
#pragma unroll
        for (int idx = threadIdx.x; idx < B * FOUT; idx += 256) {
            int bb = idx >> 6, f = idx & 63;
            float acc2 = 0.f;
#pragma unroll
            for (int k = 0; k < FIN; k++)
                acc2 += __ldcg(&d_v[bb * FIN + k]) * W[k * FOUT + f];
            out[idx] = acc2 * (1.0f / (float)N);
        }
    }
}

extern "C" void kernel_launch(void* const* d_in, const int* in_sizes, int n_in,
                              void* d_out, int out_size) {
    (void)in_sizes; (void)n_in; (void)out_size;
    const float* h = (const float*)d_in[0];
    const float* W = (const float*)d_in[1];
    const float* a = (const float*)d_in[2];
    float* out = (float*)d_out;

    k_prep<<<1, 1024>>>(W, a);
    k_scores<<<(B * N) / 8, 256>>>(h);
    k_attn<<<B, 1024>>>();
    k_wsum<<<B * 64, 256>>>(h, W, out);
}

// round 9
// speedup vs baseline: 1.0777x; 1.0777x over previous
#include <cuda_runtime.h>
#include <cuda_bf16.h>
#include <math.h>

// GAT layer, fully collapsed:
//   s1 = h @ (W a1), s2 = h @ (W a2)
//   m_i = leaky(s1_i + max_j s2_j)
//   Z_i = e^{s1_i-m_i} * SUM_{s2_j > -s1_i} e^{s2_j} + e^{.2 s1_i-m_i} * SUM_{s2_j <= -s1_i} e^{.2 s2_j}
//   c_j = e^{s2_j} * SUM_{s1_i > -s2_j} g1_i + e^{.2 s2_j} * SUM_{s1_i <= -s2_j} g2_i
//   out[b] = (1/N) * (c^T h) @ W
// Threshold sums via 1024-bin bucket structure: histogram atomic returns the
// in-bin rank (one atomic per element), scatter is atomic-free, bin sums are
// gathered + shuffle-scanned. Branch selection is exact fp compare.

#define B 8
#define N 2048
#define FIN 128
#define FOUT 64
#define ALPHA 0.2f
#define NB 1024

__device__ float d_u1[FIN];
__device__ float d_u2[FIN];
__device__ float d_s1[B * N];
__device__ float d_s2[B * N];
__device__ float d_c[B * N];
__device__ float d_v[B * FIN];

__device__ __forceinline__ float leaky(float x) { return x >= 0.f ? x : ALPHA * x; }

__device__ __forceinline__ int binOf(float x, float lo, float scale) {
    float f = (x - lo) * scale;
    f = fminf(fmaxf(f, 0.f), (float)(NB - 1));
    return (int)f;
}

// ---------------- K1: u1 = W a1, u2 = W a2; zero d_v ----------------
__global__ void k_prep(const float* __restrict__ W, const float* __restrict__ a) {
    int t = threadIdx.x;            // 1024 threads
    d_v[t] = 0.f;                   // B*FIN = 1024
    if (t < FIN) {
        float a1 = 0.f, a2 = 0.f;
#pragma unroll
        for (int f = 0; f < FOUT; f++) {
            float w = W[t * FOUT + f];
            a1 += w * a[f];
            a2 += w * a[FOUT + f];
        }
        d_u1[t] = a1;
        d_u2[t] = a2;
    }
}

// ---------------- K2: s1,s2 per row; one warp per row ----------------
__global__ void k_scores(const float* __restrict__ h) {
    __shared__ float su1[FIN], su2[FIN];
    int tid = threadIdx.x;          // 256 threads = 8 warps
    if (tid < FIN) { su1[tid] = d_u1[tid]; su2[tid] = d_u2[tid]; }
    __syncthreads();
    int warp = tid >> 5, lane = tid & 31;
    int row = blockIdx.x * 8 + warp;
    float4 hv = ((const float4*)h)[(size_t)row * (FIN / 4) + lane];
    int c = lane * 4;
    float a1 = hv.x * su1[c] + hv.y * su1[c + 1] + hv.z * su1[c + 2] + hv.w * su1[c + 3];
    float a2 = hv.x * su2[c] + hv.y * su2[c + 1] + hv.z * su2[c + 2] + hv.w * su2[c + 3];
#pragma unroll
    for (int o = 16; o; o >>= 1) {
        a1 += __shfl_xor_sync(0xffffffffu, a1, o);
        a2 += __shfl_xor_sync(0xffffffffu, a2, o);
    }
    if (lane == 0) { d_s1[row] = a1; d_s2[row] = a2; }
}

// Build the bucket structure for keys (k0,k1) with payloads (a,b) per thread.
// On exit: val/pA/pB hold elements in bin order, off[] bin starts,
// binA/binB exclusive bin prefixes, *totA/*totB grand totals.
__device__ __forceinline__ void build_struct(
    float k0, float k1, float a0, float a1v, float b0, float b1v,
    float lo, float scale,
    float* val, float* pA, float* pB, int* cnt, int* off,
    float* binA, float* binB,
    float* wsA, float* wsB, int* wsI,
    float* totA, float* totB,
    int tid, int lane, int wid)
{
    cnt[tid] = 0;
    __syncthreads();
    int bn0 = binOf(k0, lo, scale);
    int bn1 = binOf(k1, lo, scale);
    int rk0 = atomicAdd(&cnt[bn0], 1);
    int rk1 = atomicAdd(&cnt[bn1], 1);
    __syncthreads();

    // exclusive scan of counts -> off
    {
        int c = cnt[tid];
        int ci = c;
#pragma unroll
        for (int o = 1; o < 32; o <<= 1) {
            int cy = __shfl_up_sync(0xffffffffu, ci, o);
            if (lane >= o) ci += cy;
        }
        if (lane == 31) wsI[wid] = ci;
        __syncthreads();
        if (wid == 0) {
            int cw = wsI[lane];
            int cwi = cw;
#pragma unroll
            for (int o = 1; o < 32; o <<= 1) {
                int cy = __shfl_up_sync(0xffffffffu, cwi, o);
                if (lane >= o) cwi += cy;
            }
            wsI[lane] = cwi - cw;
        }
        __syncthreads();
        off[tid] = ci - c + wsI[wid];
        if (tid == 0) off[NB] = N;
    }
    __syncthreads();

    // scatter (atomic-free: rank from histogram)
    {
        int p0 = off[bn0] + rk0;
        int p1 = off[bn1] + rk1;
        val[p0] = k0;  pA[p0] = a0;  pB[p0] = b0;
        val[p1] = k1;  pA[p1] = a1v; pB[p1] = b1v;
    }
    __syncthreads();

    // gather per-bin sums, then combined exclusive scan over 1024 bins
    {
        int s = off[tid], e = off[tid + 1];
        float sa = 0.f, sb = 0.f;
        for (int p = s; p < e; p++) { sa += pA[p]; sb += pB[p]; }
        float ia = sa, ib = sb;
#pragma unroll
        for (int o = 1; o < 32; o <<= 1) {
            float ay = __shfl_up_sync(0xffffffffu, ia, o);
            float by = __shfl_up_sync(0xffffffffu, ib, o);
            if (lane >= o) { ia += ay; ib += by; }
        }
        if (lane == 31) { wsA[wid] = ia; wsB[wid] = ib; }
        __syncthreads();
        if (wid == 0) {
            float aw = wsA[lane], bw = wsB[lane];
            float awi = aw, bwi = bw;
#pragma unroll
            for (int o = 1; o < 32; o <<= 1) {
                float ay = __shfl_up_sync(0xffffffffu, awi, o);
                float by = __shfl_up_sync(0xffffffffu, bwi, o);
                if (lane >= o) { awi += ay; bwi += by; }
            }
            wsA[lane] = awi - aw; wsB[lane] = bwi - bw;
            if (lane == 31) { *totA = awi; *totB = bwi; }
        }
        __syncthreads();
        binA[tid] = ia - sa + wsA[wid];
        binB[tid] = ib - sb + wsB[wid];
    }
    __syncthreads();
}

// ---------------- K3: per-batch softmax column mass c[j] ----------------
__global__ void __launch_bounds__(1024, 1) k_attn() {
    int b = blockIdx.x;
    int tid = threadIdx.x;          // 1024
    int lane = tid & 31, wid = tid >> 5;

    __shared__ float val[N], pA[N], pB[N];
    __shared__ float binA[NB], binB[NB];
    __shared__ int   cnt[NB];
    __shared__ int   off[NB + 1];
    __shared__ float wsA[32], wsB[32];
    __shared__ int   wsI[32];
    __shared__ float bc[8];   // lo2,hi2,lo1,hi1,totA,totB

    float rs1[2], rs2[2];
    {
        const float* gs1 = d_s1 + b * N;
        const float* gs2 = d_s2 + b * N;
#pragma unroll
        for (int r = 0; r < 2; r++) {
            int i = tid + (r << 10);
            rs1[r] = gs1[i];
            rs2[r] = gs2[i];
        }
    }

    // min/max of s1, s2
    {
        float l1 = fminf(rs1[0], rs1[1]), h1 = fmaxf(rs1[0], rs1[1]);
        float l2 = fminf(rs2[0], rs2[1]), h2 = fmaxf(rs2[0], rs2[1]);
#pragma unroll
        for (int o = 16; o; o >>= 1) {
            l1 = fminf(l1, __shfl_xor_sync(0xffffffffu, l1, o));
            h1 = fmaxf(h1, __shfl_xor_sync(0xffffffffu, h1, o));
            l2 = fminf(l2, __shfl_xor_sync(0xffffffffu, l2, o));
            h2 = fmaxf(h2, __shfl_xor_sync(0xffffffffu, h2, o));
        }
        if (lane == 0) {
            val[wid] = l1; val[32 + wid] = h1; val[64 + wid] = l2; val[96 + wid] = h2;
        }
        __syncthreads();
        if (wid == 0) {
            float a0 = val[lane], a1m = val[32 + lane];
            float a2m = val[64 + lane], a3 = val[96 + lane];
#pragma unroll
            for (int o = 16; o; o >>= 1) {
                a0  = fminf(a0,  __shfl_xor_sync(0xffffffffu, a0, o));
                a1m = fmaxf(a1m, __shfl_xor_sync(0xffffffffu, a1m, o));
                a2m = fminf(a2m, __shfl_xor_sync(0xffffffffu, a2m, o));
                a3  = fmaxf(a3,  __shfl_xor_sync(0xffffffffu, a3, o));
            }
            if (lane == 0) { bc[0] = a2m; bc[1] = a3; bc[2] = a0; bc[3] = a1m; }
        }
        __syncthreads();
    }

    // ===== PASS 1: key = s2, payload (e^{s2}, e^{.2 s2}) =====
    float lo2 = bc[0], hi2 = bc[1];
    float scale2 = (hi2 > lo2) ? ((float)NB / (hi2 - lo2)) : 0.f;

    float eA0 = __expf(rs2[0]),          eA1 = __expf(rs2[1]);
    float eB0 = __expf(ALPHA * rs2[0]),  eB1 = __expf(ALPHA * rs2[1]);

    build_struct(rs2[0], rs2[1], eA0, eA1, eB0, eB1, lo2, scale2,
                 val, pA, pB, cnt, off, binA, binB, wsA, wsB, wsI,
                 &bc[4], &bc[5], tid, lane, wid);

    float g1[2], g2[2];
    {
        float smax = bc[1], tA = bc[4], tB = bc[5];
#pragma unroll
        for (int r = 0; r < 2; r++) {
            float s1 = rs1[r];
            float t = -s1;
            int qb = binOf(t, lo2, scale2);
            float SA = binA[qb], SB = binB[qb];
            int pe = off[qb + 1];
            for (int p = off[qb]; p < pe; p++) {
                if (val[p] <= t) { SA += pA[p]; SB += pB[p]; }
            }
            float Apos = tA - SA;               // sum e^{s2} over s2 > -s1
            float m = leaky(s1 + smax);
            float e1 = __expf(s1 - m);
            float e2 = __expf(ALPHA * s1 - m);
            float inv = 1.0f / (e1 * Apos + e2 * SB);
            g1[r] = e1 * inv;
            g2[r] = e2 * inv;
        }
    }
    __syncthreads();   // done reading pass-1 structure

    // ===== PASS 2: key = s1, payload (g1, g2) =====
    float lo1 = bc[2], hi1 = bc[3];
    float scale1 = (hi1 > lo1) ? ((float)NB / (hi1 - lo1)) : 0.f;

    build_struct(rs1[0], rs1[1], g1[0], g1[1], g2[0], g2[1], lo1, scale1,
                 val, pA, pB, cnt, off, binA, binB, wsA, wsB, wsI,
                 &bc[4], &bc[5], tid, lane, wid);

    {
        float tG1 = bc[4], tG2 = bc[5];
#pragma unroll
        for (int r = 0; r < 2; r++) {
            int j = tid + (r << 10);
            float s2 = rs2[r];
            float t = -s2;
            int qb = binOf(t, lo1, scale1);
            float SG1 = binA[qb], SG2 = binB[qb];
            int pe = off[qb + 1];
            for (int p = off[qb]; p < pe; p++) {
                if (val[p] <= t) { SG1 += pA[p]; SG2 += pB[p]; }
            }
            float P = tG1 - SG1;                // sum g1 over s1 > -s2
            float c = __expf(s2) * P + __expf(ALPHA * s2) * SG2;
            d_c[b * N + j] = c;
        }
    }
}

// ---------------- K4: v[b,:] = sum_j c[b,j] * h[b,j,:] ----------------
// 512 blocks, 8 warps x 4 rows each, float4 loads, smem reduce, 128 atomics/block
__global__ void k_wsum(const float* __restrict__ h) {
    __shared__ float red[8 * FIN];
    int b = blockIdx.x >> 6;              // grid = B*64
    int chunk = blockIdx.x & 63;
    int wid = threadIdx.x >> 5, lane = threadIdx.x & 31;   // 256 threads
    const float4* h4 = (const float4*)h;
    const float* cb = d_c + b * N;
    size_t base = (size_t)b * N * (FIN / 4);
    int j0 = chunk * 32 + wid * 4;
    float c0 = cb[j0], c1 = cb[j0 + 1], c2 = cb[j0 + 2], c3 = cb[j0 + 3];
    float4 h0 = h4[base + (size_t)(j0 + 0) * (FIN / 4) + lane];
    float4 h1 = h4[base + (size_t)(j0 + 1) * (FIN / 4) + lane];
    float4 h2 = h4[base + (size_t)(j0 + 2) * (FIN / 4) + lane];
    float4 h3 = h4[base + (size_t)(j0 + 3) * (FIN / 4) + lane];
    float4 acc;
    acc.x = c0 * h0.x + c1 * h1.x + c2 * h2.x + c3 * h3.x;
    acc.y = c0 * h0.y + c1 * h1.y + c2 * h2.y + c3 * h3.y;
    acc.z = c0 * h0.z + c1 * h1.z + c2 * h2.z + c3 * h3.z;
    acc.w = c0 * h0.w + c1 * h1.w + c2 * h2.w + c3 * h3.w;
    ((float4*)red)[wid * 32 + lane] = acc;
    __syncthreads();
    if (threadIdx.x < FIN) {
        int k = threadIdx.x;
        float s = 0.f;
#pragma unroll
        for (int w = 0; w < 8; w++) s += red[w * FIN + k];
        atomicAdd(&d_v[b * FIN + k], s);
    }
}

// ---------------- K5: out[b,f] = (1/N) * v[b,:] . W[:,f] ----------------
__global__ void k_out(const float* __restrict__ W, float* __restrict__ out) {
    int idx = threadIdx.x;                // 512 = B*FOUT
    int b = idx >> 6, f = idx & 63;
    float acc = 0.f;
#pragma unroll
    for (int k = 0; k < FIN; k++) acc += d_v[b * FIN + k] * W[k * FOUT + f];
    out[idx] = acc * (1.0f / (float)N);
}

extern "C" void kernel_launch(void* const* d_in, const int* in_sizes, int n_in,
                              void* d_out, int out_size) {
    (void)in_sizes; (void)n_in; (void)out_size;
    const float* h = (const float*)d_in[0];
    const float* W = (const float*)d_in[1];
    const float* a = (const float*)d_in[2];
    float* out = (float*)d_out;

    k_prep<<<1, 1024>>>(W, a);
    k_scores<<<(B * N) / 8, 256>>>(h);
    k_attn<<<B, 1024>>>();
    k_wsum<<<B * 64, 256>>>(h);
    k_out<<<1, 512>>>(W, out);
}